// round 1
// baseline (speedup 1.0000x reference)
#include <cuda_runtime.h>
#include <math.h>

#define B    2
#define CIN  320
#define CENC 326
#define DK   64
#define DV   64
#define L    4096

// ---------------- scratch (device globals; no allocation allowed) ----------------
__device__ float g_Qn[B * L * DK];   // [b][l][d]  L2-normalized Q
__device__ float g_Kn[B * L * DK];   // [b][l][d]  L2-normalized K
__device__ float g_V [B * L * DV];   // [b][l][v]
__device__ float g_Wtq[CENC * DK];   // W transposed: [c][d]
__device__ float g_Wtk[CENC * DK];
__device__ float g_Wtv[CIN  * DV];

// ---------------- weight transpose: W[d][c] -> Wt[c][d] ----------------
__global__ void transpose_w_kernel(const float* __restrict__ W, int Cin, int which) {
    float* Wt = (which == 0) ? g_Wtq : (which == 1) ? g_Wtk : g_Wtv;
    int idx = blockIdx.x * blockDim.x + threadIdx.x;
    if (idx < 64 * Cin) {
        int d = idx / Cin;
        int c = idx - d * Cin;
        Wt[c * 64 + d] = W[idx];
    }
}

// ---------------- fused Q/K projection + bias + L2 normalize ----------------
// grid: (L/64, B), block: 256.  thread: ll = t&63 (position), dg = t>>6 (16 d's)
__global__ __launch_bounds__(256) void proj_qk_kernel(const float* __restrict__ x_enc,
                                                      const float* __restrict__ bq,
                                                      const float* __restrict__ bk) {
    int t  = threadIdx.x;
    int ll = t & 63;
    int dg = t >> 6;                  // 0..3
    int b  = blockIdx.y;
    int l  = blockIdx.x * 64 + ll;

    float qa[16], ka[16];
#pragma unroll
    for (int k = 0; k < 16; ++k) { qa[k] = 0.f; ka[k] = 0.f; }

    const float* xe = x_enc + (size_t)b * CENC * L + l;
    const float4* wq4 = (const float4*)(g_Wtq) + dg * 4;   // + c*16 per step
    const float4* wk4 = (const float4*)(g_Wtk) + dg * 4;

#pragma unroll 2
    for (int c = 0; c < CENC; ++c) {
        float xv = __ldg(xe + (size_t)c * L);
        const float4* wq = wq4 + c * 16;
        const float4* wk = wk4 + c * 16;
#pragma unroll
        for (int k = 0; k < 4; ++k) {
            float4 w = __ldg(wq + k);
            qa[4*k+0] += w.x * xv; qa[4*k+1] += w.y * xv;
            qa[4*k+2] += w.z * xv; qa[4*k+3] += w.w * xv;
            float4 u = __ldg(wk + k);
            ka[4*k+0] += u.x * xv; ka[4*k+1] += u.y * xv;
            ka[4*k+2] += u.z * xv; ka[4*k+3] += u.w * xv;
        }
    }

    float sq = 0.f, sk = 0.f;
#pragma unroll
    for (int k = 0; k < 16; ++k) {
        qa[k] += __ldg(bq + dg * 16 + k);
        ka[k] += __ldg(bk + dg * 16 + k);
        sq += qa[k] * qa[k];
        sk += ka[k] * ka[k];
    }

    __shared__ float redq[4][64];
    __shared__ float redk[4][64];
    redq[dg][ll] = sq;
    redk[dg][ll] = sk;
    __syncthreads();
    float nq = redq[0][ll] + redq[1][ll] + redq[2][ll] + redq[3][ll];
    float nk = redk[0][ll] + redk[1][ll] + redk[2][ll] + redk[3][ll];
    float scq = 1.f / fmaxf(sqrtf(nq), 1e-6f);
    float sck = 1.f / fmaxf(sqrtf(nk), 1e-6f);

    float* qdst = g_Qn + ((size_t)b * L + l) * DK + dg * 16;
    float* kdst = g_Kn + ((size_t)b * L + l) * DK + dg * 16;
#pragma unroll
    for (int k = 0; k < 4; ++k) {
        float4 qo = make_float4(qa[4*k+0]*scq, qa[4*k+1]*scq, qa[4*k+2]*scq, qa[4*k+3]*scq);
        float4 ko = make_float4(ka[4*k+0]*sck, ka[4*k+1]*sck, ka[4*k+2]*sck, ka[4*k+3]*sck);
        ((float4*)qdst)[k] = qo;
        ((float4*)kdst)[k] = ko;
    }
}

// ---------------- V projection + bias ----------------
__global__ __launch_bounds__(256) void proj_v_kernel(const float* __restrict__ x,
                                                     const float* __restrict__ bv) {
    int t  = threadIdx.x;
    int ll = t & 63;
    int dg = t >> 6;
    int b  = blockIdx.y;
    int l  = blockIdx.x * 64 + ll;

    float va[16];
#pragma unroll
    for (int k = 0; k < 16; ++k) va[k] = 0.f;

    const float* xf = x + (size_t)b * CIN * L + l;
    const float4* wv4 = (const float4*)(g_Wtv) + dg * 4;

#pragma unroll 2
    for (int c = 0; c < CIN; ++c) {
        float xv = __ldg(xf + (size_t)c * L);
        const float4* wv = wv4 + c * 16;
#pragma unroll
        for (int k = 0; k < 4; ++k) {
            float4 w = __ldg(wv + k);
            va[4*k+0] += w.x * xv; va[4*k+1] += w.y * xv;
            va[4*k+2] += w.z * xv; va[4*k+3] += w.w * xv;
        }
    }

    float* vdst = g_V + ((size_t)b * L + l) * DV + dg * 16;
#pragma unroll
    for (int k = 0; k < 4; ++k) {
        float4 vo = make_float4(va[4*k+0] + __ldg(bv + dg*16 + 4*k + 0),
                                va[4*k+1] + __ldg(bv + dg*16 + 4*k + 1),
                                va[4*k+2] + __ldg(bv + dg*16 + 4*k + 2),
                                va[4*k+3] + __ldg(bv + dg*16 + 4*k + 3));
        ((float4*)vdst)[k] = vo;
    }
}

// ---------------- fused cosine attention (no rescale needed: scores in [-1,1]) ----
// grid: (L/TI, B), block 256. TI=32 queries, TJ=64 key tile.
#define TI 32
#define TJ 64
#define QPAD 68   // row stride for Q tile: conflict-free quarter-warp LDS.128

__global__ __launch_bounds__(256) void attn_kernel(float* __restrict__ out) {
    extern __shared__ float sm[];
    float* Qs = sm;                       // [TI][QPAD]
    float* Ks = Qs + TI * QPAD;           // [TJ][QPAD]
    float* Vs = Ks + TJ * QPAD;           // [TJ][64]
    float* Ps = Vs + TJ * 64;             // [TJ][TI]  (j-major for conflict-free i reads)

    int t   = threadIdx.x;
    int il  = t & 31;          // query row within tile
    int grp = t >> 5;          // 0..7 : j-group (phase1) / v-group (phase2)
    int b   = blockIdx.y;
    int i0  = blockIdx.x * TI;

    // load Q tile (TI x 64) -> padded shared
    for (int idx = t; idx < TI * 16; idx += 256) {
        int r = idx >> 4, c4 = idx & 15;
        float4 q = ((const float4*)(g_Qn + ((size_t)b * L + i0 + r) * DK))[c4];
        *(float4*)&Qs[r * QPAD + c4 * 4] = q;
    }

    float acc[8];
#pragma unroll
    for (int k = 0; k < 8; ++k) acc[k] = 0.f;
    float dsum = 0.f;

    for (int j0 = 0; j0 < L; j0 += TJ) {
        __syncthreads();   // protect prior-tile Ps/Ks/Vs consumers
        // load K, V tiles (each TJ x 64 floats)
        for (int idx = t; idx < TJ * 16; idx += 256) {
            int r = idx >> 4, c4 = idx & 15;
            float4 kv = ((const float4*)(g_Kn + ((size_t)b * L + j0 + r) * DK))[c4];
            *(float4*)&Ks[r * QPAD + c4 * 4] = kv;
            float4 vv = ((const float4*)(g_V + ((size_t)b * L + j0 + r) * DV))[c4];
            *(float4*)&Vs[r * 64 + c4 * 4] = vv;
        }
        __syncthreads();

        // phase 1: 8 scores per thread: S[il][grp*8+jj] = dot64(Q[il], K[j])
        float s[8];
#pragma unroll
        for (int jj = 0; jj < 8; ++jj) s[jj] = 0.f;
#pragma unroll
        for (int c = 0; c < 64; c += 4) {
            float4 q = *(const float4*)&Qs[il * QPAD + c];
#pragma unroll
            for (int jj = 0; jj < 8; ++jj) {
                float4 kk = *(const float4*)&Ks[(grp * 8 + jj) * QPAD + c];
                s[jj] += q.x * kk.x + q.y * kk.y + q.z * kk.z + q.w * kk.w;
            }
        }
#pragma unroll
        for (int jj = 0; jj < 8; ++jj)
            Ps[(grp * 8 + jj) * TI + il] = __expf(s[jj]);
        __syncthreads();

        // phase 2: acc[v] += P[j][il] * V[j][grp*8+v];  denom += P
#pragma unroll 4
        for (int j = 0; j < TJ; ++j) {
            float p = Ps[j * TI + il];
            dsum += p;
            float4 v0 = *(const float4*)&Vs[j * 64 + grp * 8];
            float4 v1 = *(const float4*)&Vs[j * 64 + grp * 8 + 4];
            acc[0] += p * v0.x; acc[1] += p * v0.y;
            acc[2] += p * v0.z; acc[3] += p * v0.w;
            acc[4] += p * v1.x; acc[5] += p * v1.y;
            acc[6] += p * v1.z; acc[7] += p * v1.w;
        }
    }

    // write: out[b][v][i] = acc[v] / denom
    float inv = 1.f / dsum;           // dsum >= L*e^-1 > 0, always finite
    int i = i0 + il;
#pragma unroll
    for (int k = 0; k < 8; ++k)
        out[((size_t)b * DV + grp * 8 + k) * L + i] = acc[k] * inv;
}

// ---------------- launch ----------------
extern "C" void kernel_launch(void* const* d_in, const int* in_sizes, int n_in,
                              void* d_out, int out_size) {
    const float* x     = (const float*)d_in[0];
    const float* x_enc = (const float*)d_in[1];
    const float* Wq    = (const float*)d_in[2];
    const float* bq    = (const float*)d_in[3];
    const float* Wk    = (const float*)d_in[4];
    const float* bk    = (const float*)d_in[5];
    const float* Wv    = (const float*)d_in[6];
    const float* bv    = (const float*)d_in[7];
    float* out = (float*)d_out;

    // weight transposes
    transpose_w_kernel<<<(64 * CENC + 255) / 256, 256>>>(Wq, CENC, 0);
    transpose_w_kernel<<<(64 * CENC + 255) / 256, 256>>>(Wk, CENC, 1);
    transpose_w_kernel<<<(64 * CIN  + 255) / 256, 256>>>(Wv, CIN, 2);

    // projections
    proj_qk_kernel<<<dim3(L / 64, B), 256>>>(x_enc, bq, bk);
    proj_v_kernel <<<dim3(L / 64, B), 256>>>(x, bv);

    // fused attention
    int smem = (TI * QPAD + TJ * QPAD + TJ * 64 + TJ * TI) * (int)sizeof(float);
    static bool attr_set = false;
    if (!attr_set) {
        cudaFuncSetAttribute(attn_kernel, cudaFuncAttributeMaxDynamicSharedMemorySize, smem);
        attr_set = true;
    }
    attn_kernel<<<dim3(L / TI, B), 256, smem>>>(out);
}